// round 1
// baseline (speedup 1.0000x reference)
#include <cuda_runtime.h>

#define N_NODES 100000
#define N_EDGES 1600000
#define D 64

// ---------------- scratch (no allocs allowed) ----------------
__device__ float g_agg[(size_t)N_NODES * D];   // 25.6 MB
__device__ float g_h[(size_t)N_NODES * D];     // 25.6 MB (layer-1 output)
__device__ float g_cnt[N_NODES];               // in-degree as float
__device__ int   g_is64;                       // edge_index dtype flag

// ---------------- dtype detection ----------------
// int64 little-endian with values < 2^31 => every high 32-bit word is 0.
// int32 random values in [0,100000) => essentially impossible that 1024
// consecutive odd-position words are all zero.
__global__ void detect_kernel(const unsigned int* __restrict__ w) {
    __shared__ int any_nz;
    if (threadIdx.x == 0) any_nz = 0;
    __syncthreads();
    int nz = 0;
#pragma unroll
    for (int j = 0; j < 4; j++) {
        int pos = (threadIdx.x * 4 + j) * 2 + 1;   // high word if int64
        if (w[pos] != 0u) nz = 1;
    }
    if (nz) atomicOr(&any_nz, 1);
    __syncthreads();
    if (threadIdx.x == 0) g_is64 = any_nz ? 0 : 1;
}

// ---------------- zeroing ----------------
__global__ __launch_bounds__(256) void zero_kernel(int with_cnt) {
    long long i = (long long)blockIdx.x * 256 + threadIdx.x;
    const long long NA = (long long)N_NODES * D / 4;   // 1.6M float4
    float4 z = make_float4(0.f, 0.f, 0.f, 0.f);
    if (i < NA) {
        ((float4*)g_agg)[i] = z;
    } else if (with_cnt) {
        long long j = i - NA;
        if (j < N_NODES / 4) ((float4*)g_cnt)[j] = z;
    }
}

// ---------------- edge aggregation ----------------
__device__ __forceinline__ void red_add4(float* addr, float4 v) {
    asm volatile("red.global.add.v4.f32 [%0], {%1,%2,%3,%4};"
                 :: "l"(addr), "f"(v.x), "f"(v.y), "f"(v.z), "f"(v.w)
                 : "memory");
}

__device__ __forceinline__ long long edge_idx(const void* ei, long long pos, int is64) {
    return is64 ? ((const long long*)ei)[pos]
                : (long long)((const int*)ei)[pos];
}

// one thread per (edge, 16B chunk): 16 threads/edge
__global__ __launch_bounds__(256) void agg_kernel(const float* __restrict__ feat_param,
                                                  const void* __restrict__ ei,
                                                  int count_pass) {
    long long t = (long long)blockIdx.x * 256 + threadIdx.x;
    long long e = t >> 4;
    int c = (int)(t & 15);
    if (e >= N_EDGES) return;
    const float* feat = feat_param ? feat_param : g_h;
    int is64 = g_is64;
    long long src = edge_idx(ei, e, is64);
    long long dst = edge_idx(ei, (long long)N_EDGES + e, is64);
    float4 v = *(const float4*)(feat + src * D + c * 4);
    red_add4(g_agg + dst * D + c * 4, v);
    if (count_pass && c == 0) atomicAdd(g_cnt + dst, 1.0f);
}

// ---------------- fused SAGE layer: out = mean@Wl^T + feat@Wr^T + b ----------------
// Block: 64 nodes x 64 output cols, 256 threads, each computes a 4x4 tile.
// SMEM is k-major so both compute operands are contiguous LDS.128.
__global__ __launch_bounds__(256) void layer_kernel(const float* __restrict__ feat_param,
                                                    const float* __restrict__ Wl,
                                                    const float* __restrict__ Wr,
                                                    const float* __restrict__ b,
                                                    float* __restrict__ out_param,
                                                    int do_relu) {
    __shared__ float Xs[64][64];       // [k][node]
    __shared__ float Ws[64][68];       // [k][col], padded
    __shared__ float bsh[64];

    const float* feat = feat_param ? feat_param : g_h;
    float* out = out_param ? out_param : g_h;

    int tid = threadIdx.x;
    int tc = tid & 15;        // col group (4 cols)
    int tn = tid >> 4;        // node group (4 nodes)
    int nb = blockIdx.x * 64;

    if (tid < 64) bsh[tid] = b[tid];

    float acc[4][4];
#pragma unroll
    for (int i = 0; i < 4; i++)
#pragma unroll
        for (int j = 0; j < 4; j++) acc[i][j] = 0.f;

#pragma unroll
    for (int phase = 0; phase < 2; phase++) {
        const float* W = phase ? Wr : Wl;

        // load W (transpose into k-major): item -> c = item&63, kc = item>>6
#pragma unroll
        for (int it = 0; it < 4; it++) {
            int item = it * 256 + tid;
            int c = item & 63, kc = item >> 6;     // kc in 0..15
            float4 w = *(const float4*)(W + c * 64 + kc * 4);
            Ws[kc * 4 + 0][c] = w.x;
            Ws[kc * 4 + 1][c] = w.y;
            Ws[kc * 4 + 2][c] = w.z;
            Ws[kc * 4 + 3][c] = w.w;
        }
        // load X (phase 0: mean = agg/max(cnt,1); phase 1: feat), transpose to k-major
#pragma unroll
        for (int it = 0; it < 4; it++) {
            int item = it * 256 + tid;
            int n = item & 63, kc = item >> 6;
            int node = nb + n;
            float4 v = make_float4(0.f, 0.f, 0.f, 0.f);
            if (node < N_NODES) {
                if (phase == 0) {
                    float cn = fmaxf(g_cnt[node], 1.0f);
                    float inv = 1.0f / cn;
                    float4 a = *(const float4*)(g_agg + (size_t)node * D + kc * 4);
                    v = make_float4(a.x * inv, a.y * inv, a.z * inv, a.w * inv);
                } else {
                    v = *(const float4*)(feat + (size_t)node * D + kc * 4);
                }
            }
            Xs[kc * 4 + 0][n] = v.x;
            Xs[kc * 4 + 1][n] = v.y;
            Xs[kc * 4 + 2][n] = v.z;
            Xs[kc * 4 + 3][n] = v.w;
        }
        __syncthreads();

#pragma unroll 8
        for (int k = 0; k < 64; k++) {
            float4 xv = *(const float4*)&Xs[k][tn * 4];
            float4 wv = *(const float4*)&Ws[k][tc * 4];
            acc[0][0] += xv.x * wv.x; acc[0][1] += xv.x * wv.y;
            acc[0][2] += xv.x * wv.z; acc[0][3] += xv.x * wv.w;
            acc[1][0] += xv.y * wv.x; acc[1][1] += xv.y * wv.y;
            acc[1][2] += xv.y * wv.z; acc[1][3] += xv.y * wv.w;
            acc[2][0] += xv.z * wv.x; acc[2][1] += xv.z * wv.y;
            acc[2][2] += xv.z * wv.z; acc[2][3] += xv.z * wv.w;
            acc[3][0] += xv.w * wv.x; acc[3][1] += xv.w * wv.y;
            acc[3][2] += xv.w * wv.z; acc[3][3] += xv.w * wv.w;
        }
        __syncthreads();
    }

    // epilogue: bias (+ relu), vectorized store
#pragma unroll
    for (int i = 0; i < 4; i++) {
        int node = nb + tn * 4 + i;
        if (node < N_NODES) {
            float4 o;
            o.x = acc[i][0] + bsh[tc * 4 + 0];
            o.y = acc[i][1] + bsh[tc * 4 + 1];
            o.z = acc[i][2] + bsh[tc * 4 + 2];
            o.w = acc[i][3] + bsh[tc * 4 + 3];
            if (do_relu) {
                o.x = fmaxf(o.x, 0.f); o.y = fmaxf(o.y, 0.f);
                o.z = fmaxf(o.z, 0.f); o.w = fmaxf(o.w, 0.f);
            }
            *(float4*)(out + (size_t)node * D + tc * 4) = o;
        }
    }
}

// ---------------- launch ----------------
extern "C" void kernel_launch(void* const* d_in, const int* in_sizes, int n_in,
                              void* d_out, int out_size) {
    const float* x   = (const float*)d_in[0];
    const void*  ei  = d_in[1];
    const float* W1l = (const float*)d_in[2];
    const float* W1r = (const float*)d_in[3];
    const float* b1  = (const float*)d_in[4];
    const float* W2l = (const float*)d_in[5];
    const float* W2r = (const float*)d_in[6];
    const float* b2  = (const float*)d_in[7];
    float* out = (float*)d_out;

    const int ZERO_BLOCKS_ALL = (N_NODES * D / 4 + N_NODES / 4 + 255) / 256;
    const int ZERO_BLOCKS_AGG = (N_NODES * D / 4 + 255) / 256;
    const int AGG_BLOCKS  = (int)(((long long)N_EDGES * 16 + 255) / 256);
    const int MM_BLOCKS   = (N_NODES + 63) / 64;

    detect_kernel<<<1, 256>>>((const unsigned int*)ei);

    // layer 1
    zero_kernel<<<ZERO_BLOCKS_ALL, 256>>>(1);
    agg_kernel<<<AGG_BLOCKS, 256>>>(x, ei, 1);
    layer_kernel<<<MM_BLOCKS, 256>>>(x, W1l, W1r, b1, nullptr, 1);   // -> g_h, relu

    // layer 2
    zero_kernel<<<ZERO_BLOCKS_AGG, 256>>>(0);
    agg_kernel<<<AGG_BLOCKS, 256>>>(nullptr, ei, 0);                  // gather g_h
    layer_kernel<<<MM_BLOCKS, 256>>>(nullptr, W2l, W2r, b2, out, 0);  // -> d_out
}

// round 3
// speedup vs baseline: 1.4259x; 1.4259x over previous
#include <cuda_runtime.h>

#define N_NODES 100000
#define N_EDGES 1600000
#define D 64
#define SCAN_TILE 1024
#define SCAN_NBLK ((N_NODES + SCAN_TILE - 1) / SCAN_TILE)   // 98

// ---------------- scratch (no allocs allowed) ----------------
__device__ float g_agg[(size_t)N_NODES * D];   // 25.6 MB (neighbor sums)
__device__ float g_h[(size_t)N_NODES * D];     // 25.6 MB (layer-1 output)
__device__ int   g_deg[N_NODES];               // in-degree
__device__ int   g_off[N_NODES];               // CSR exclusive offsets
__device__ int   g_pos[N_NODES];               // scatter cursors
__device__ int   g_part[SCAN_NBLK + 8];        // scan partials
__device__ int   g_csr[N_EDGES];               // CSR src indices
__device__ int   g_is64;                       // edge_index dtype flag

// ---------------- dtype detection ----------------
__global__ void detect_kernel(const unsigned int* __restrict__ w) {
    __shared__ int any_nz;
    if (threadIdx.x == 0) any_nz = 0;
    __syncthreads();
    int nz = 0;
#pragma unroll
    for (int j = 0; j < 4; j++) {
        int pos = (threadIdx.x * 4 + j) * 2 + 1;   // high word if int64
        if (w[pos] != 0u) nz = 1;
    }
    if (nz) atomicOr(&any_nz, 1);
    __syncthreads();
    if (threadIdx.x == 0) g_is64 = any_nz ? 0 : 1;
}

__device__ __forceinline__ int edge_idx(const void* ei, long long pos, int is64) {
    return is64 ? (int)((const long long*)ei)[pos]
                : ((const int*)ei)[pos];
}

// ---------------- CSR build ----------------
__global__ __launch_bounds__(256) void zero_deg_kernel() {
    int i = blockIdx.x * 256 + threadIdx.x;
    if (i < N_NODES) g_deg[i] = 0;
}

__global__ __launch_bounds__(256) void hist_kernel(const void* __restrict__ ei) {
    int e = blockIdx.x * 256 + threadIdx.x;
    if (e >= N_EDGES) return;
    int dst = edge_idx(ei, (long long)N_EDGES + e, g_is64);
    atomicAdd(&g_deg[dst], 1);
}

// per-block exclusive scan of deg (tile = 1024), block totals to g_part
__global__ __launch_bounds__(256) void scan_local_kernel() {
    int base = blockIdx.x * SCAN_TILE;
    int idx0 = base + threadIdx.x * 4;
    int v[4];
#pragma unroll
    for (int j = 0; j < 4; j++)
        v[j] = (idx0 + j < N_NODES) ? g_deg[idx0 + j] : 0;
    int tsum = v[0] + v[1] + v[2] + v[3];

    int lane = threadIdx.x & 31, wid = threadIdx.x >> 5;
    int s = tsum;
#pragma unroll
    for (int o = 1; o < 32; o <<= 1) {
        int t = __shfl_up_sync(0xffffffffu, s, o);
        if (lane >= o) s += t;
    }
    __shared__ int wsum[8];
    if (lane == 31) wsum[wid] = s;
    __syncthreads();
    if (wid == 0) {
        int ws = (lane < 8) ? wsum[lane] : 0;
#pragma unroll
        for (int o = 1; o < 8; o <<= 1) {
            int t = __shfl_up_sync(0xffffffffu, ws, o);
            if (lane >= o) ws += t;
        }
        if (lane < 8) wsum[lane] = ws;
    }
    __syncthreads();
    int excl = s - tsum + (wid > 0 ? wsum[wid - 1] : 0);
    int run = excl;
#pragma unroll
    for (int j = 0; j < 4; j++) {
        if (idx0 + j < N_NODES) g_off[idx0 + j] = run;
        run += v[j];
    }
    if (threadIdx.x == 255) g_part[blockIdx.x] = run;   // block total
}

// exclusive scan of g_part (SCAN_NBLK <= 128), single block of 128
__global__ void scan_part_kernel() {
    int tid = threadIdx.x;
    int v = (tid < SCAN_NBLK) ? g_part[tid] : 0;
    int lane = tid & 31, wid = tid >> 5;
    int s = v;
#pragma unroll
    for (int o = 1; o < 32; o <<= 1) {
        int t = __shfl_up_sync(0xffffffffu, s, o);
        if (lane >= o) s += t;
    }
    __shared__ int wsum[4];
    if (lane == 31) wsum[wid] = s;
    __syncthreads();
    if (wid == 0 && lane < 4) {
        int ws = wsum[lane];
#pragma unroll
        for (int o = 1; o < 4; o <<= 1) {
            int t = __shfl_up_sync(0x0000000fu, ws, o);
            if (lane >= o) ws += t;
        }
        wsum[lane] = ws;
    }
    __syncthreads();
    int excl = s - v + (wid > 0 ? wsum[wid - 1] : 0);
    if (tid < SCAN_NBLK) g_part[tid] = excl;
}

__global__ __launch_bounds__(256) void scan_add_kernel() {
    int i = blockIdx.x * 256 + threadIdx.x;
    if (i >= N_NODES) return;
    int o = g_off[i] + g_part[i / SCAN_TILE];
    g_off[i] = o;
    g_pos[i] = o;
}

__global__ __launch_bounds__(256) void scatter_kernel(const void* __restrict__ ei) {
    int e = blockIdx.x * 256 + threadIdx.x;
    if (e >= N_EDGES) return;
    int is64 = g_is64;
    int src = edge_idx(ei, e, is64);
    int dst = edge_idx(ei, (long long)N_EDGES + e, is64);
    int p = atomicAdd(&g_pos[dst], 1);
    g_csr[p] = src;
}

// ---------------- CSR aggregation: g_agg[node] = sum_{j in N(node)} feat[j] ----------------
// 16 threads per node, each owns one float4 chunk. Register accumulation,
// single coalesced 256B store per node. Fully overwrites g_agg (no zeroing).
__global__ __launch_bounds__(256) void agg_csr_kernel(const float* __restrict__ feat_param) {
    int t = blockIdx.x * 256 + threadIdx.x;
    int node = t >> 4;
    int c = t & 15;
    if (node >= N_NODES) return;
    const float* feat = feat_param ? feat_param : g_h;
    const int beg = g_off[node];
    const int n = g_deg[node];
    float4 acc = make_float4(0.f, 0.f, 0.f, 0.f);
    int j = 0;
    for (; j + 4 <= n; j += 4) {
        int s0 = g_csr[beg + j + 0];
        int s1 = g_csr[beg + j + 1];
        int s2 = g_csr[beg + j + 2];
        int s3 = g_csr[beg + j + 3];
        float4 v0 = *(const float4*)(feat + (size_t)s0 * D + c * 4);
        float4 v1 = *(const float4*)(feat + (size_t)s1 * D + c * 4);
        float4 v2 = *(const float4*)(feat + (size_t)s2 * D + c * 4);
        float4 v3 = *(const float4*)(feat + (size_t)s3 * D + c * 4);
        acc.x += v0.x + v1.x + v2.x + v3.x;
        acc.y += v0.y + v1.y + v2.y + v3.y;
        acc.z += v0.z + v1.z + v2.z + v3.z;
        acc.w += v0.w + v1.w + v2.w + v3.w;
    }
    for (; j < n; j++) {
        int s = g_csr[beg + j];
        float4 v = *(const float4*)(feat + (size_t)s * D + c * 4);
        acc.x += v.x; acc.y += v.y; acc.z += v.z; acc.w += v.w;
    }
    *(float4*)(g_agg + (size_t)node * D + c * 4) = acc;
}

// ---------------- fused SAGE layer: out = (sum/max(deg,1))@Wl^T + feat@Wr^T + b ----------------
__global__ __launch_bounds__(256) void layer_kernel(const float* __restrict__ feat_param,
                                                    const float* __restrict__ Wl,
                                                    const float* __restrict__ Wr,
                                                    const float* __restrict__ b,
                                                    float* __restrict__ out_param,
                                                    int do_relu) {
    __shared__ float Xs[64][64];       // [k][node]
    __shared__ float Ws[64][68];       // [k][col], padded
    __shared__ float bsh[64];

    const float* feat = feat_param ? feat_param : g_h;
    float* out = out_param ? out_param : g_h;

    int tid = threadIdx.x;
    int tc = tid & 15;        // col group (4 cols)
    int tn = tid >> 4;        // node group (4 nodes)
    int nb = blockIdx.x * 64;

    if (tid < 64) bsh[tid] = b[tid];

    float acc[4][4];
#pragma unroll
    for (int i = 0; i < 4; i++)
#pragma unroll
        for (int j = 0; j < 4; j++) acc[i][j] = 0.f;

#pragma unroll
    for (int phase = 0; phase < 2; phase++) {
        const float* W = phase ? Wr : Wl;

#pragma unroll
        for (int it = 0; it < 4; it++) {
            int item = it * 256 + tid;
            int c = item & 63, kc = item >> 6;
            float4 w = *(const float4*)(W + c * 64 + kc * 4);
            Ws[kc * 4 + 0][c] = w.x;
            Ws[kc * 4 + 1][c] = w.y;
            Ws[kc * 4 + 2][c] = w.z;
            Ws[kc * 4 + 3][c] = w.w;
        }
#pragma unroll
        for (int it = 0; it < 4; it++) {
            int item = it * 256 + tid;
            int n = item & 63, kc = item >> 6;
            int node = nb + n;
            float4 v = make_float4(0.f, 0.f, 0.f, 0.f);
            if (node < N_NODES) {
                if (phase == 0) {
                    float cn = fmaxf((float)g_deg[node], 1.0f);
                    float inv = 1.0f / cn;
                    float4 a = *(const float4*)(g_agg + (size_t)node * D + kc * 4);
                    v = make_float4(a.x * inv, a.y * inv, a.z * inv, a.w * inv);
                } else {
                    v = *(const float4*)(feat + (size_t)node * D + kc * 4);
                }
            }
            Xs[kc * 4 + 0][n] = v.x;
            Xs[kc * 4 + 1][n] = v.y;
            Xs[kc * 4 + 2][n] = v.z;
            Xs[kc * 4 + 3][n] = v.w;
        }
        __syncthreads();

#pragma unroll 8
        for (int k = 0; k < 64; k++) {
            float4 xv = *(const float4*)&Xs[k][tn * 4];
            float4 wv = *(const float4*)&Ws[k][tc * 4];
            acc[0][0] += xv.x * wv.x; acc[0][1] += xv.x * wv.y;
            acc[0][2] += xv.x * wv.z; acc[0][3] += xv.x * wv.w;
            acc[1][0] += xv.y * wv.x; acc[1][1] += xv.y * wv.y;
            acc[1][2] += xv.y * wv.z; acc[1][3] += xv.y * wv.w;
            acc[2][0] += xv.z * wv.x; acc[2][1] += xv.z * wv.y;
            acc[2][2] += xv.z * wv.z; acc[2][3] += xv.z * wv.w;
            acc[3][0] += xv.w * wv.x; acc[3][1] += xv.w * wv.y;
            acc[3][2] += xv.w * wv.z; acc[3][3] += xv.w * wv.w;
        }
        __syncthreads();
    }

#pragma unroll
    for (int i = 0; i < 4; i++) {
        int node = nb + tn * 4 + i;
        if (node < N_NODES) {
            float4 o;
            o.x = acc[i][0] + bsh[tc * 4 + 0];
            o.y = acc[i][1] + bsh[tc * 4 + 1];
            o.z = acc[i][2] + bsh[tc * 4 + 2];
            o.w = acc[i][3] + bsh[tc * 4 + 3];
            if (do_relu) {
                o.x = fmaxf(o.x, 0.f); o.y = fmaxf(o.y, 0.f);
                o.z = fmaxf(o.z, 0.f); o.w = fmaxf(o.w, 0.f);
            }
            *(float4*)(out + (size_t)node * D + tc * 4) = o;
        }
    }
}

// ---------------- launch ----------------
extern "C" void kernel_launch(void* const* d_in, const int* in_sizes, int n_in,
                              void* d_out, int out_size) {
    const float* x   = (const float*)d_in[0];
    const void*  ei  = d_in[1];
    const float* W1l = (const float*)d_in[2];
    const float* W1r = (const float*)d_in[3];
    const float* b1  = (const float*)d_in[4];
    const float* W2l = (const float*)d_in[5];
    const float* W2r = (const float*)d_in[6];
    const float* b2  = (const float*)d_in[7];
    float* out = (float*)d_out;

    const int E_BLOCKS   = (N_EDGES + 255) / 256;
    const int N_BLOCKS   = (N_NODES + 255) / 256;
    const int AGG_BLOCKS = (N_NODES * 16 + 255) / 256;
    const int MM_BLOCKS  = (N_NODES + 63) / 64;

    detect_kernel<<<1, 256>>>((const unsigned int*)ei);

    // CSR build (once, reused by both layers)
    zero_deg_kernel<<<N_BLOCKS, 256>>>();
    hist_kernel<<<E_BLOCKS, 256>>>(ei);
    scan_local_kernel<<<SCAN_NBLK, 256>>>();
    scan_part_kernel<<<1, 128>>>();
    scan_add_kernel<<<N_BLOCKS, 256>>>();
    scatter_kernel<<<E_BLOCKS, 256>>>(ei);

    // layer 1
    agg_csr_kernel<<<AGG_BLOCKS, 256>>>(x);
    layer_kernel<<<MM_BLOCKS, 256>>>(x, W1l, W1r, b1, nullptr, 1);   // -> g_h, relu

    // layer 2
    agg_csr_kernel<<<AGG_BLOCKS, 256>>>(nullptr);                     // gather g_h
    layer_kernel<<<MM_BLOCKS, 256>>>(nullptr, W2l, W2r, b2, out, 0);  // -> d_out
}

// round 4
// speedup vs baseline: 1.5354x; 1.0767x over previous
#include <cuda_runtime.h>

#define N_NODES 100000
#define N_EDGES 1600000
#define D 64
#define SCAN_TILE 1024
#define SCAN_NBLK ((N_NODES + SCAN_TILE - 1) / SCAN_TILE)   // 98

// ---------------- scratch (no allocs allowed) ----------------
__device__ float g_agg[(size_t)N_NODES * D];   // 25.6 MB (neighbor sums)
__device__ float g_h[(size_t)N_NODES * D];     // 25.6 MB (layer-1 output)
__device__ int   g_deg[N_NODES];               // in-degree
__device__ int   g_off[N_NODES];               // CSR exclusive offsets
__device__ int   g_pos[N_NODES];               // scatter cursors
__device__ int   g_part[SCAN_NBLK + 8];        // scan partials
__device__ int   g_csr[N_EDGES];               // CSR src indices
__device__ int   g_is64;                       // edge_index dtype flag

// ---------------- dtype detection + deg zeroing (fused) ----------------
__global__ __launch_bounds__(256) void detect_zero_kernel(const unsigned int* __restrict__ w) {
    int i = blockIdx.x * 256 + threadIdx.x;
    if (i < N_NODES) g_deg[i] = 0;
    if (blockIdx.x == 0) {
        __shared__ int any_nz;
        if (threadIdx.x == 0) any_nz = 0;
        __syncthreads();
        int nz = 0;
#pragma unroll
        for (int j = 0; j < 4; j++) {
            int pos = (threadIdx.x * 4 + j) * 2 + 1;   // high word if int64
            if (w[pos] != 0u) nz = 1;
        }
        if (nz) atomicOr(&any_nz, 1);
        __syncthreads();
        if (threadIdx.x == 0) g_is64 = any_nz ? 0 : 1;
    }
}

__device__ __forceinline__ int edge_idx(const void* ei, long long pos, int is64) {
    return is64 ? (int)((const long long*)ei)[pos]
                : ((const int*)ei)[pos];
}

// ---------------- CSR build ----------------
__global__ __launch_bounds__(256) void hist_kernel(const void* __restrict__ ei) {
    int e = blockIdx.x * 256 + threadIdx.x;
    if (e >= N_EDGES) return;
    int dst = edge_idx(ei, (long long)N_EDGES + e, g_is64);
    atomicAdd(&g_deg[dst], 1);
}

// per-block exclusive scan of deg (tile = 1024), block totals to g_part
__global__ __launch_bounds__(256) void scan_local_kernel() {
    int base = blockIdx.x * SCAN_TILE;
    int idx0 = base + threadIdx.x * 4;
    int v[4];
#pragma unroll
    for (int j = 0; j < 4; j++)
        v[j] = (idx0 + j < N_NODES) ? g_deg[idx0 + j] : 0;
    int tsum = v[0] + v[1] + v[2] + v[3];

    int lane = threadIdx.x & 31, wid = threadIdx.x >> 5;
    int s = tsum;
#pragma unroll
    for (int o = 1; o < 32; o <<= 1) {
        int t = __shfl_up_sync(0xffffffffu, s, o);
        if (lane >= o) s += t;
    }
    __shared__ int wsum[8];
    if (lane == 31) wsum[wid] = s;
    __syncthreads();
    if (wid == 0) {
        int ws = (lane < 8) ? wsum[lane] : 0;
#pragma unroll
        for (int o = 1; o < 8; o <<= 1) {
            int t = __shfl_up_sync(0xffffffffu, ws, o);
            if (lane >= o) ws += t;
        }
        if (lane < 8) wsum[lane] = ws;
    }
    __syncthreads();
    int excl = s - tsum + (wid > 0 ? wsum[wid - 1] : 0);
    int run = excl;
#pragma unroll
    for (int j = 0; j < 4; j++) {
        if (idx0 + j < N_NODES) g_off[idx0 + j] = run;
        run += v[j];
    }
    if (threadIdx.x == 255) g_part[blockIdx.x] = run;   // block total
}

// exclusive scan of g_part (SCAN_NBLK <= 128), single block of 128
__global__ void scan_part_kernel() {
    int tid = threadIdx.x;
    int v = (tid < SCAN_NBLK) ? g_part[tid] : 0;
    int lane = tid & 31, wid = tid >> 5;
    int s = v;
#pragma unroll
    for (int o = 1; o < 32; o <<= 1) {
        int t = __shfl_up_sync(0xffffffffu, s, o);
        if (lane >= o) s += t;
    }
    __shared__ int wsum[4];
    if (lane == 31) wsum[wid] = s;
    __syncthreads();
    if (wid == 0 && lane < 4) {
        int ws = wsum[lane];
#pragma unroll
        for (int o = 1; o < 4; o <<= 1) {
            int t = __shfl_up_sync(0x0000000fu, ws, o);
            if (lane >= o) ws += t;
        }
        wsum[lane] = ws;
    }
    __syncthreads();
    int excl = s - v + (wid > 0 ? wsum[wid - 1] : 0);
    if (tid < SCAN_NBLK) g_part[tid] = excl;
}

__global__ __launch_bounds__(256) void scan_add_kernel() {
    int i = blockIdx.x * 256 + threadIdx.x;
    if (i >= N_NODES) return;
    int o = g_off[i] + g_part[i / SCAN_TILE];
    g_off[i] = o;
    g_pos[i] = o;
}

__global__ __launch_bounds__(256) void scatter_kernel(const void* __restrict__ ei) {
    int e = blockIdx.x * 256 + threadIdx.x;
    if (e >= N_EDGES) return;
    int is64 = g_is64;
    int src = edge_idx(ei, e, is64);
    int dst = edge_idx(ei, (long long)N_EDGES + e, is64);
    int p = atomicAdd(&g_pos[dst], 1);
    g_csr[p] = src;
}

// ---------------- CSR aggregation: g_agg[node] = sum_{j in N(node)} feat[j] ----------------
__global__ __launch_bounds__(256) void agg_csr_kernel(const float* __restrict__ feat_param) {
    int t = blockIdx.x * 256 + threadIdx.x;
    int node = t >> 4;
    int c = t & 15;
    if (node >= N_NODES) return;
    const float* feat = feat_param ? feat_param : g_h;
    const int beg = g_off[node];
    const int n = g_deg[node];
    float4 acc = make_float4(0.f, 0.f, 0.f, 0.f);
    int j = 0;
    for (; j + 4 <= n; j += 4) {
        int s0 = g_csr[beg + j + 0];
        int s1 = g_csr[beg + j + 1];
        int s2 = g_csr[beg + j + 2];
        int s3 = g_csr[beg + j + 3];
        float4 v0 = *(const float4*)(feat + (size_t)s0 * D + c * 4);
        float4 v1 = *(const float4*)(feat + (size_t)s1 * D + c * 4);
        float4 v2 = *(const float4*)(feat + (size_t)s2 * D + c * 4);
        float4 v3 = *(const float4*)(feat + (size_t)s3 * D + c * 4);
        acc.x += v0.x + v1.x + v2.x + v3.x;
        acc.y += v0.y + v1.y + v2.y + v3.y;
        acc.z += v0.z + v1.z + v2.z + v3.z;
        acc.w += v0.w + v1.w + v2.w + v3.w;
    }
    for (; j < n; j++) {
        int s = g_csr[beg + j];
        float4 v = *(const float4*)(feat + (size_t)s * D + c * 4);
        acc.x += v.x; acc.y += v.y; acc.z += v.z; acc.w += v.w;
    }
    *(float4*)(g_agg + (size_t)node * D + c * 4) = acc;
}

// ---------------- fused SAGE layer: out = (sum/max(deg,1))@Wl^T + feat@Wr^T + b ----------------
// Block tile: 128 nodes x 64 cols, 256 threads, each thread 8 nodes x 4 cols.
// LDS per k = 48B per 32 lane-FMAs (1.5 B/FMA) -> FMA-bound, crossbar at 75%.
__global__ __launch_bounds__(256) void layer_kernel(const float* __restrict__ feat_param,
                                                    const float* __restrict__ Wl,
                                                    const float* __restrict__ Wr,
                                                    const float* __restrict__ b,
                                                    float* __restrict__ out_param,
                                                    int do_relu) {
    __shared__ float Xs[64][128];      // [k][node]
    __shared__ float Ws[64][68];       // [k][col], padded
    __shared__ float bsh[64];

    const float* feat = feat_param ? feat_param : g_h;
    float* out = out_param ? out_param : g_h;

    int tid = threadIdx.x;
    int tc = tid & 15;        // col group (4 cols)
    int tn = tid >> 4;        // node group (8 nodes)
    int nb = blockIdx.x * 128;

    if (tid < 64) bsh[tid] = b[tid];

    float acc[8][4];
#pragma unroll
    for (int i = 0; i < 8; i++)
#pragma unroll
        for (int j = 0; j < 4; j++) acc[i][j] = 0.f;

#pragma unroll
    for (int phase = 0; phase < 2; phase++) {
        const float* W = phase ? Wr : Wl;

        // load W (transpose into k-major): 1024 float4 items? no: 64x64 floats
        // = 1024 float4; 256 threads x 4 items
#pragma unroll
        for (int it = 0; it < 4; it++) {
            int item = it * 256 + tid;
            int c = item & 63, kc = item >> 6;     // kc in 0..15
            float4 w = *(const float4*)(W + c * 64 + kc * 4);
            Ws[kc * 4 + 0][c] = w.x;
            Ws[kc * 4 + 1][c] = w.y;
            Ws[kc * 4 + 2][c] = w.z;
            Ws[kc * 4 + 3][c] = w.w;
        }
        // load X tile: 128 nodes x 64 k = 2048 float4 items; 256 threads x 8
#pragma unroll
        for (int it = 0; it < 8; it++) {
            int item = it * 256 + tid;
            int n = item & 127, kc = item >> 7;     // kc in 0..15
            int node = nb + n;
            float4 v = make_float4(0.f, 0.f, 0.f, 0.f);
            if (node < N_NODES) {
                if (phase == 0) {
                    float cn = fmaxf((float)g_deg[node], 1.0f);
                    float inv = 1.0f / cn;
                    float4 a = *(const float4*)(g_agg + (size_t)node * D + kc * 4);
                    v = make_float4(a.x * inv, a.y * inv, a.z * inv, a.w * inv);
                } else {
                    v = *(const float4*)(feat + (size_t)node * D + kc * 4);
                }
            }
            Xs[kc * 4 + 0][n] = v.x;
            Xs[kc * 4 + 1][n] = v.y;
            Xs[kc * 4 + 2][n] = v.z;
            Xs[kc * 4 + 3][n] = v.w;
        }
        __syncthreads();

#pragma unroll 8
        for (int k = 0; k < 64; k++) {
            float4 xa = *(const float4*)&Xs[k][tn * 8];
            float4 xb = *(const float4*)&Xs[k][tn * 8 + 4];
            float4 wv = *(const float4*)&Ws[k][tc * 4];
            acc[0][0] += xa.x * wv.x; acc[0][1] += xa.x * wv.y;
            acc[0][2] += xa.x * wv.z; acc[0][3] += xa.x * wv.w;
            acc[1][0] += xa.y * wv.x; acc[1][1] += xa.y * wv.y;
            acc[1][2] += xa.y * wv.z; acc[1][3] += xa.y * wv.w;
            acc[2][0] += xa.z * wv.x; acc[2][1] += xa.z * wv.y;
            acc[2][2] += xa.z * wv.z; acc[2][3] += xa.z * wv.w;
            acc[3][0] += xa.w * wv.x; acc[3][1] += xa.w * wv.y;
            acc[3][2] += xa.w * wv.z; acc[3][3] += xa.w * wv.w;
            acc[4][0] += xb.x * wv.x; acc[4][1] += xb.x * wv.y;
            acc[4][2] += xb.x * wv.z; acc[4][3] += xb.x * wv.w;
            acc[5][0] += xb.y * wv.x; acc[5][1] += xb.y * wv.y;
            acc[5][2] += xb.y * wv.z; acc[5][3] += xb.y * wv.w;
            acc[6][0] += xb.z * wv.x; acc[6][1] += xb.z * wv.y;
            acc[6][2] += xb.z * wv.z; acc[6][3] += xb.z * wv.w;
            acc[7][0] += xb.w * wv.x; acc[7][1] += xb.w * wv.y;
            acc[7][2] += xb.w * wv.z; acc[7][3] += xb.w * wv.w;
        }
        __syncthreads();
    }

    // epilogue: bias (+ relu), vectorized store
    float4 bv = *(const float4*)&bsh[tc * 4];
#pragma unroll
    for (int i = 0; i < 8; i++) {
        int node = nb + tn * 8 + i;
        if (node < N_NODES) {
            float4 o;
            o.x = acc[i][0] + bv.x;
            o.y = acc[i][1] + bv.y;
            o.z = acc[i][2] + bv.z;
            o.w = acc[i][3] + bv.w;
            if (do_relu) {
                o.x = fmaxf(o.x, 0.f); o.y = fmaxf(o.y, 0.f);
                o.z = fmaxf(o.z, 0.f); o.w = fmaxf(o.w, 0.f);
            }
            *(float4*)(out + (size_t)node * D + tc * 4) = o;
        }
    }
}

// ---------------- launch ----------------
extern "C" void kernel_launch(void* const* d_in, const int* in_sizes, int n_in,
                              void* d_out, int out_size) {
    const float* x   = (const float*)d_in[0];
    const void*  ei  = d_in[1];
    const float* W1l = (const float*)d_in[2];
    const float* W1r = (const float*)d_in[3];
    const float* b1  = (const float*)d_in[4];
    const float* W2l = (const float*)d_in[5];
    const float* W2r = (const float*)d_in[6];
    const float* b2  = (const float*)d_in[7];
    float* out = (float*)d_out;

    const int E_BLOCKS   = (N_EDGES + 255) / 256;
    const int N_BLOCKS   = (N_NODES + 255) / 256;
    const int AGG_BLOCKS = (N_NODES * 16 + 255) / 256;
    const int MM_BLOCKS  = (N_NODES + 127) / 128;

    // CSR build (once, reused by both layers)
    detect_zero_kernel<<<N_BLOCKS, 256>>>((const unsigned int*)ei);
    hist_kernel<<<E_BLOCKS, 256>>>(ei);
    scan_local_kernel<<<SCAN_NBLK, 256>>>();
    scan_part_kernel<<<1, 128>>>();
    scan_add_kernel<<<N_BLOCKS, 256>>>();
    scatter_kernel<<<E_BLOCKS, 256>>>(ei);

    // layer 1
    agg_csr_kernel<<<AGG_BLOCKS, 256>>>(x);
    layer_kernel<<<MM_BLOCKS, 256>>>(x, W1l, W1r, b1, nullptr, 1);   // -> g_h, relu

    // layer 2
    agg_csr_kernel<<<AGG_BLOCKS, 256>>>(nullptr);                     // gather g_h
    layer_kernel<<<MM_BLOCKS, 256>>>(nullptr, W2l, W2r, b2, out, 0);  // -> d_out
}

// round 5
// speedup vs baseline: 1.5865x; 1.0333x over previous
#include <cuda_runtime.h>

#define N_NODES 100000
#define N_EDGES 1600000
#define D 64
#define SCAN_TILE 1024
#define SCAN_NBLK ((N_NODES + SCAN_TILE - 1) / SCAN_TILE)   // 98

// ---------------- scratch (no allocs allowed) ----------------
__device__ float g_h[(size_t)N_NODES * D];     // 25.6 MB (layer-1 output)
__device__ int   g_deg[N_NODES];               // in-degree
__device__ int   g_off[N_NODES];               // CSR exclusive offsets
__device__ int   g_pos[N_NODES];               // scatter cursors
__device__ int   g_csr[N_EDGES];               // CSR src indices
__device__ unsigned long long g_status[SCAN_NBLK];  // lookback: flag<<32 | sum

// ---------------- inline dtype detection (per-warp, no global flag) ----------------
// int64 edge values < 2^31 -> all high words zero. For int32 data the odd
// words are uniform node ids; P(32 consecutive all zero) ~ 0.
__device__ __forceinline__ int warp_is64(const unsigned* __restrict__ w) {
    unsigned v = w[2 * (threadIdx.x & 31) + 1];
    return __ballot_sync(0xffffffffu, v != 0) == 0;
}

__device__ __forceinline__ int edge_at(const void* ei, long long pos, int is64) {
    return is64 ? (int)((const long long*)ei)[pos]
                : ((const int*)ei)[pos];
}

// ---------------- CSR build ----------------
__global__ __launch_bounds__(256) void hist_kernel(const void* __restrict__ ei) {
    int is64 = warp_is64((const unsigned*)ei);
    int e = blockIdx.x * 256 + threadIdx.x;
    if (e >= N_EDGES) return;
    int dst = edge_at(ei, (long long)N_EDGES + e, is64);
    atomicAdd(&g_deg[dst], 1);
}

// single-pass exclusive scan with decoupled lookback.
// 98 blocks, all co-resident on 148 SMs -> spin is deadlock-free.
__global__ __launch_bounds__(256) void scan_lookback_kernel() {
    const unsigned FULL = 0xffffffffu;
    int b = blockIdx.x;
    int base = b * SCAN_TILE;
    int idx0 = base + threadIdx.x * 4;
    int v[4];
#pragma unroll
    for (int j = 0; j < 4; j++)
        v[j] = (idx0 + j < N_NODES) ? g_deg[idx0 + j] : 0;
    int tsum = v[0] + v[1] + v[2] + v[3];

    int lane = threadIdx.x & 31, wid = threadIdx.x >> 5;
    int s = tsum;
#pragma unroll
    for (int o = 1; o < 32; o <<= 1) {
        int t = __shfl_up_sync(FULL, s, o);
        if (lane >= o) s += t;
    }
    __shared__ int wsum[8];
    __shared__ int sprefix;
    if (lane == 31) wsum[wid] = s;
    __syncthreads();
    if (wid == 0) {
        int ws = (lane < 8) ? wsum[lane] : 0;
#pragma unroll
        for (int o = 1; o < 8; o <<= 1) {
            int t = __shfl_up_sync(FULL, ws, o);
            if (lane >= o) ws += t;
        }
        if (lane < 8) wsum[lane] = ws;
    }
    __syncthreads();
    int excl = s - tsum + (wid > 0 ? wsum[wid - 1] : 0);
    int total = wsum[7];

    if (wid == 7) {
        // publish: block 0 publishes PREFIX immediately, others AGG
        if (lane == 31) {
            unsigned long long pk =
                ((unsigned long long)(b == 0 ? 2u : 1u) << 32) | (unsigned)total;
            atomicExch(&g_status[b], pk);
        }
        int prefix = 0;
        if (b > 0) {
            int w = 0;
            bool done = false;
            while (!done) {
                int idx = b - 32 * (w + 1) + lane;
                int flag, val;
                do {
                    if (idx >= 0) {
                        unsigned long long st = atomicAdd(&g_status[idx], 0ULL);
                        flag = (int)(st >> 32);
                        val = (int)(st & 0xffffffffu);
                    } else { flag = 2; val = 0; }
                } while (__ballot_sync(FULL, flag == 0));
                unsigned m2 = __ballot_sync(FULL, flag == 2);
                int contrib;
                if (m2) {
                    int h = 31 - __clz(m2);          // highest prefix lane
                    contrib = (lane >= h) ? val : 0;
                    done = true;
                } else {
                    contrib = val;
                    w++;
                }
#pragma unroll
                for (int o = 16; o; o >>= 1)
                    contrib += __shfl_down_sync(FULL, contrib, o);
                prefix += __shfl_sync(FULL, contrib, 0);
            }
            if (lane == 31)
                atomicExch(&g_status[b],
                           (2ULL << 32) | (unsigned)(prefix + total));
        }
        if (lane == 0) sprefix = prefix;
    }
    __syncthreads();

    int run = excl + sprefix;
#pragma unroll
    for (int j = 0; j < 4; j++) {
        if (idx0 + j < N_NODES) { g_off[idx0 + j] = run; g_pos[idx0 + j] = run; }
        run += v[j];
    }
}

__global__ __launch_bounds__(256) void scatter_kernel(const void* __restrict__ ei) {
    int is64 = warp_is64((const unsigned*)ei);
    int e = blockIdx.x * 256 + threadIdx.x;
    if (e >= N_EDGES) return;
    int src = edge_at(ei, e, is64);
    int dst = edge_at(ei, (long long)N_EDGES + e, is64);
    int p = atomicAdd(&g_pos[dst], 1);
    g_csr[p] = src;
}

// ---------------- fused SAGE layer ----------------
// out = mean_{j in N(i)} feat[j] @ Wl^T + feat @ Wr^T + b   (+relu)
// Block: 128 nodes x 64 cols, 256 threads, each thread 8 nodes x 4 cols.
// Phase A gathers the mean tile straight from CSR (no g_agg round-trip);
// blocks pipeline gather (L2) against FMA across the grid.
// Xs is node-major: conflict-free STS from gather, broadcast LDS in FMA.
__device__ __forceinline__ void mm_tile(const float (*__restrict__ Xs)[64],
                                        const float (*__restrict__ Ws)[64],
                                        float acc[8][4], int tn, int tc) {
#pragma unroll 2
    for (int k4 = 0; k4 < 64; k4 += 4) {
        float4 w0 = *(const float4*)&Ws[k4 + 0][tc * 4];
        float4 w1 = *(const float4*)&Ws[k4 + 1][tc * 4];
        float4 w2 = *(const float4*)&Ws[k4 + 2][tc * 4];
        float4 w3 = *(const float4*)&Ws[k4 + 3][tc * 4];
#pragma unroll
        for (int i = 0; i < 8; i++) {
            float4 xv = *(const float4*)&Xs[tn * 8 + i][k4];
            acc[i][0] += xv.x * w0.x + xv.y * w1.x + xv.z * w2.x + xv.w * w3.x;
            acc[i][1] += xv.x * w0.y + xv.y * w1.y + xv.z * w2.y + xv.w * w3.y;
            acc[i][2] += xv.x * w0.z + xv.y * w1.z + xv.z * w2.z + xv.w * w3.z;
            acc[i][3] += xv.x * w0.w + xv.y * w1.w + xv.z * w2.w + xv.w * w3.w;
        }
    }
}

__device__ __forceinline__ void load_w(float (*__restrict__ Ws)[64],
                                       const float* __restrict__ W, int tid) {
#pragma unroll
    for (int it = 0; it < 4; it++) {
        int item = it * 256 + tid;
        int c = item & 63, kc = item >> 6;     // kc in 0..15
        float4 w = *(const float4*)(W + c * 64 + kc * 4);
        Ws[kc * 4 + 0][c] = w.x;
        Ws[kc * 4 + 1][c] = w.y;
        Ws[kc * 4 + 2][c] = w.z;
        Ws[kc * 4 + 3][c] = w.w;
    }
}

__global__ __launch_bounds__(256) void fused_layer_kernel(const float* __restrict__ feat_param,
                                                          const float* __restrict__ Wl,
                                                          const float* __restrict__ Wr,
                                                          const float* __restrict__ b,
                                                          float* __restrict__ out_param,
                                                          int do_relu) {
    __shared__ float Xs[128][64];      // node-major tile (32 KB)
    __shared__ float Ws[64][64];       // k-major weights (16 KB)

    const float* feat = feat_param ? feat_param : g_h;
    float* out = out_param ? out_param : g_h;

    int tid = threadIdx.x;
    int tc = tid & 15;        // col group (4 cols)
    int tn = tid >> 4;        // node group (8 nodes)
    int nb = blockIdx.x * 128;

    float acc[8][4];
#pragma unroll
    for (int i = 0; i < 8; i++)
#pragma unroll
        for (int j = 0; j < 4; j++) acc[i][j] = 0.f;

    // ---- Phase A: mean tile via CSR gather + Wl ----
    load_w(Ws, Wl, tid);
    {
        int c = tid & 15;         // float4 chunk of the row
        int g = tid >> 4;         // node subgroup
        const float* fp = feat + c * 4;
#pragma unroll 1
        for (int pass = 0; pass < 8; pass++) {
            int n_local = pass * 16 + g;
            int node = nb + n_local;
            float4 a = make_float4(0.f, 0.f, 0.f, 0.f);
            float inv = 0.f;
            if (node < N_NODES) {
                int beg = g_off[node];
                int n = g_deg[node];
                inv = 1.0f / fmaxf((float)n, 1.0f);
                int j = 0;
                for (; j + 4 <= n; j += 4) {
                    int s0 = g_csr[beg + j + 0];
                    int s1 = g_csr[beg + j + 1];
                    int s2 = g_csr[beg + j + 2];
                    int s3 = g_csr[beg + j + 3];
                    float4 v0 = *(const float4*)(fp + (size_t)s0 * D);
                    float4 v1 = *(const float4*)(fp + (size_t)s1 * D);
                    float4 v2 = *(const float4*)(fp + (size_t)s2 * D);
                    float4 v3 = *(const float4*)(fp + (size_t)s3 * D);
                    a.x += v0.x + v1.x + v2.x + v3.x;
                    a.y += v0.y + v1.y + v2.y + v3.y;
                    a.z += v0.z + v1.z + v2.z + v3.z;
                    a.w += v0.w + v1.w + v2.w + v3.w;
                }
                for (; j < n; j++) {
                    int sidx = g_csr[beg + j];
                    float4 v = *(const float4*)(fp + (size_t)sidx * D);
                    a.x += v.x; a.y += v.y; a.z += v.z; a.w += v.w;
                }
            }
            *(float4*)&Xs[n_local][c * 4] =
                make_float4(a.x * inv, a.y * inv, a.z * inv, a.w * inv);
        }
    }
    __syncthreads();
    mm_tile(Xs, Ws, acc, tn, tc);
    __syncthreads();

    // ---- Phase B: self features + Wr ----
    load_w(Ws, Wr, tid);
#pragma unroll
    for (int it = 0; it < 8; it++) {
        int item = it * 256 + tid;
        int kc = item & 15, n = item >> 4;     // 16 chunks x 128 nodes
        int node = nb + n;
        float4 v = make_float4(0.f, 0.f, 0.f, 0.f);
        if (node < N_NODES)
            v = *(const float4*)(feat + (size_t)node * D + kc * 4);
        *(float4*)&Xs[n][kc * 4] = v;
    }
    __syncthreads();
    mm_tile(Xs, Ws, acc, tn, tc);

    // ---- epilogue: bias (+relu), vectorized store ----
    float4 bv = *(const float4*)&b[tc * 4];
#pragma unroll
    for (int i = 0; i < 8; i++) {
        int node = nb + tn * 8 + i;
        if (node < N_NODES) {
            float4 o;
            o.x = acc[i][0] + bv.x;
            o.y = acc[i][1] + bv.y;
            o.z = acc[i][2] + bv.z;
            o.w = acc[i][3] + bv.w;
            if (do_relu) {
                o.x = fmaxf(o.x, 0.f); o.y = fmaxf(o.y, 0.f);
                o.z = fmaxf(o.z, 0.f); o.w = fmaxf(o.w, 0.f);
            }
            *(float4*)(out + (size_t)node * D + tc * 4) = o;
        }
    }
}

// ---------------- launch ----------------
extern "C" void kernel_launch(void* const* d_in, const int* in_sizes, int n_in,
                              void* d_out, int out_size) {
    const float* x   = (const float*)d_in[0];
    const void*  ei  = d_in[1];
    const float* W1l = (const float*)d_in[2];
    const float* W1r = (const float*)d_in[3];
    const float* b1  = (const float*)d_in[4];
    const float* W2l = (const float*)d_in[5];
    const float* W2r = (const float*)d_in[6];
    const float* b2  = (const float*)d_in[7];
    float* out = (float*)d_out;

    const int E_BLOCKS  = (N_EDGES + 255) / 256;
    const int MM_BLOCKS = (N_NODES + 127) / 128;

    void* p_deg = nullptr;
    void* p_st  = nullptr;
    cudaGetSymbolAddress(&p_deg, g_deg);
    cudaGetSymbolAddress(&p_st, g_status);
    cudaMemsetAsync(p_deg, 0, N_NODES * sizeof(int), 0);
    cudaMemsetAsync(p_st, 0, SCAN_NBLK * sizeof(unsigned long long), 0);

    // CSR build (once, reused by both layers)
    hist_kernel<<<E_BLOCKS, 256>>>(ei);
    scan_lookback_kernel<<<SCAN_NBLK, 256>>>();
    scatter_kernel<<<E_BLOCKS, 256>>>(ei);

    // fused layers (gather + GEMM in one kernel)
    fused_layer_kernel<<<MM_BLOCKS, 256>>>(x, W1l, W1r, b1, nullptr, 1);   // -> g_h
    fused_layer_kernel<<<MM_BLOCKS, 256>>>(nullptr, W2l, W2r, b2, out, 0); // -> d_out
}